// round 9
// baseline (speedup 1.0000x reference)
#include <cuda_runtime.h>
#include <cuda_bf16.h>
#include <math.h>
#include <stdint.h>

// Shapes (fixed)
#define BB 32
#define TT 512
#define AA 64
#define DD 128
#define HH 256
#define MM (BB*TT)     // 16384
#define NN (DD*DD)     // 16384
#define KK HH          // 256
#define KSPLIT 768     // 3*KK : A=[hi|hi|lo], B=[hi|lo|hi]

// Device scratch (allocation-free rule)
__device__ __align__(128) __nv_bfloat16 g_A2[(size_t)MM * KSPLIT];   // 25 MB
__device__ __align__(128) __nv_bfloat16 g_B2T[(size_t)NN * KSPLIT];  // 25 MB
__device__ __align__(128) float g_trans[(size_t)MM * NN];            // 1.07 GB

// ---------------------------------------------------------------------------
// PTX helpers (sm_80-class only — harness ptxas targets base sm_103)
// ---------------------------------------------------------------------------
__device__ __forceinline__ uint32_t smem_u32(const void* p) {
    uint32_t a;
    asm("{ .reg .u64 t; cvta.to.shared.u64 t, %1; cvt.u32.u64 %0, t; }" : "=r"(a) : "l"(p));
    return a;
}
__device__ __forceinline__ void cp16(uint32_t dst, const void* src) {
    asm volatile("cp.async.cg.shared.global [%0], [%1], 16;" :: "r"(dst), "l"(src) : "memory");
}
__device__ __forceinline__ void cp_commit() {
    asm volatile("cp.async.commit_group;" ::: "memory");
}
template <int N>
__device__ __forceinline__ void cp_wait() {
    asm volatile("cp.async.wait_group %0;" :: "n"(N) : "memory");
}
__device__ __forceinline__ void ldsm4(uint32_t* r, uint32_t addr) {
    asm volatile("ldmatrix.sync.aligned.m8n8.x4.shared.b16 {%0,%1,%2,%3}, [%4];"
                 : "=r"(r[0]), "=r"(r[1]), "=r"(r[2]), "=r"(r[3]) : "r"(addr));
}
__device__ __forceinline__ void mma_bf16(float* d, const uint32_t* a, const uint32_t* b) {
    asm volatile(
        "mma.sync.aligned.m16n8k16.row.col.f32.bf16.bf16.f32 "
        "{%0,%1,%2,%3}, {%4,%5,%6,%7}, {%8,%9}, {%0,%1,%2,%3};"
        : "+f"(d[0]), "+f"(d[1]), "+f"(d[2]), "+f"(d[3])
        : "r"(a[0]), "r"(a[1]), "r"(a[2]), "r"(a[3]), "r"(b[0]), "r"(b[1]));
}
// SW128 swizzle, closed form for row*128+kb (kb < 128)
__device__ __forceinline__ uint32_t swoff(uint32_t row, uint32_t kb) {
    return row * 128u + (kb ^ ((row & 7u) << 4));
}

// ---------------------------------------------------------------------------
// Kernel 1: h = relu(actions@w1+b1); write A2 = [hi | hi | lo] bf16 rows
// ---------------------------------------------------------------------------
__global__ __launch_bounds__(256) void mlp1_kernel(const float* __restrict__ actions,
                                                   const float* __restrict__ w1,
                                                   const float* __restrict__ b1)
{
    __shared__ float as[8][AA];
    const int tid = threadIdx.x;
    const int m0 = blockIdx.x * 8;

    for (int i = tid; i < 8 * AA; i += 256)
        as[i >> 6][i & 63] = actions[(size_t)m0 * AA + i];
    __syncthreads();

    const int n = tid;
    float bv = b1[n];
    float acc[8];
#pragma unroll
    for (int r = 0; r < 8; r++) acc[r] = bv;
#pragma unroll 8
    for (int a = 0; a < AA; a++) {
        float w = w1[(size_t)a * HH + n];
#pragma unroll
        for (int r = 0; r < 8; r++) acc[r] = fmaf(as[r][a], w, acc[r]);
    }
#pragma unroll
    for (int r = 0; r < 8; r++) {
        float v = fmaxf(acc[r], 0.0f);
        __nv_bfloat16 hi = __float2bfloat16_rn(v);
        __nv_bfloat16 lo = __float2bfloat16_rn(v - __bfloat162float(hi));
        size_t row = (size_t)(m0 + r) * KSPLIT;
        g_A2[row + n] = hi;
        g_A2[row + KK + n] = hi;
        g_A2[row + 2 * KK + n] = lo;
    }
}

// ---------------------------------------------------------------------------
// Kernel 1b: B2T[n, :] = [hi(w2[:,n]) | lo(w2[:,n]) | hi(w2[:,n])]  (transpose)
// ---------------------------------------------------------------------------
__global__ __launch_bounds__(256) void bprep_kernel(const float* __restrict__ w2)
{
    __shared__ float tile[32][33];
    const int tx = threadIdx.x;          // 0..31
    const int ty = threadIdx.y;          // 0..7
    const int n0 = blockIdx.x * 32;
    const int k0 = blockIdx.y * 32;
#pragma unroll
    for (int i = 0; i < 4; i++) {
        int k = k0 + ty + i * 8;
        tile[ty + i * 8][tx] = w2[(size_t)k * NN + n0 + tx];
    }
    __syncthreads();
#pragma unroll
    for (int i = 0; i < 4; i++) {
        int nrow = ty + i * 8;
        float v = tile[tx][nrow];        // w2[k0+tx, n0+nrow]
        __nv_bfloat16 hi = __float2bfloat16_rn(v);
        __nv_bfloat16 lo = __float2bfloat16_rn(v - __bfloat162float(hi));
        size_t row = (size_t)(n0 + nrow) * KSPLIT + k0 + tx;
        g_B2T[row] = hi;
        g_B2T[row + KK] = lo;
        g_B2T[row + 2 * KK] = hi;
    }
}

// ---------------------------------------------------------------------------
// Kernel 2: bf16 mma.sync GEMM (R7/R8 measured-good config, unchanged)
// BM=128, BN=128, BK=64 (SW128), 3-stage cp.async, 256 threads, 2 CTAs/SM.
// ---------------------------------------------------------------------------
#define BMG 128
#define BNG 128
#define BKG 64
#define NKT (KSPLIT/BKG)     // 12
#define NSTG 3
#define A_BYTES (BMG*128)    // 16384
#define B_BYTES (BNG*128)    // 16384
#define STAGE_BYTES (A_BYTES + B_BYTES)  // 32768

__global__ __launch_bounds__(256, 2) void gemm7_kernel(const float* __restrict__ bias)
{
    extern __shared__ char dsm[];
    __shared__ float bias_s[BNG];

    const uint32_t dyn = smem_u32(dsm);
    const int tid = threadIdx.x;
    const int wid = tid >> 5;
    const int lane = tid & 31;
    const int m0 = blockIdx.y * BMG;
    const int n0 = blockIdx.x * BNG;

    if (tid < BNG) bias_s[tid] = bias[n0 + tid];

    const char* Abase = (const char*)g_A2;
    const char* Bbase = (const char*)g_B2T;

    auto load_stage = [&](int s, int kt) {
        uint32_t sb = dyn + s * STAGE_BYTES;
        size_t kbyte = (size_t)kt * (BKG * 2);
#pragma unroll
        for (int i = 0; i < 4; i++) {
            int q = i * 256 + tid;
            uint32_t r = q >> 3, c = (q & 7) * 16;
            cp16(sb + swoff(r, c),
                 Abase + (size_t)(m0 + r) * (KSPLIT * 2) + kbyte + c);
        }
#pragma unroll
        for (int i = 0; i < 4; i++) {
            int q = i * 256 + tid;
            uint32_t r = q >> 3, c = (q & 7) * 16;
            cp16(sb + A_BYTES + swoff(r, c),
                 Bbase + (size_t)(n0 + r) * (KSPLIT * 2) + kbyte + c);
        }
        cp_commit();
    };

    load_stage(0, 0);
    load_stage(1, 1);

    const int m_w = (wid >> 2) * 64;
    const int n_w = (wid & 3) * 32;

    const uint32_t a_row = m_w + (lane & 7) + (lane & 8);
    const uint32_t a_kb  = (lane >> 4) << 4;
    const uint32_t b_row = n_w + (lane & 7) + ((lane >> 4) << 3);
    const uint32_t b_kb  = (lane & 8) << 1;

    float acc[4][4][4];
#pragma unroll
    for (int mi = 0; mi < 4; mi++)
#pragma unroll
        for (int nt = 0; nt < 4; nt++)
#pragma unroll
            for (int e = 0; e < 4; e++) acc[mi][nt][e] = 0.0f;

#pragma unroll 1
    for (int kt = 0; kt < NKT; kt++) {
        const int s = kt % NSTG;

        if (kt + 1 < NKT) cp_wait<1>();
        else              cp_wait<0>();
        __syncthreads();

        if (kt + 2 < NKT) load_stage((kt + 2) % NSTG, kt + 2);

        const uint32_t abase = dyn + s * STAGE_BYTES;
        const uint32_t bbase = abase + A_BYTES;

#pragma unroll
        for (int ks = 0; ks < 4; ks++) {
            uint32_t af[4][4], bf[2][4];
#pragma unroll
            for (int mi = 0; mi < 4; mi++)
                ldsm4(af[mi], abase + swoff(a_row + mi * 16, a_kb + ks * 32));
#pragma unroll
            for (int nj = 0; nj < 2; nj++)
                ldsm4(bf[nj], bbase + swoff(b_row + nj * 16, b_kb + ks * 32));
#pragma unroll
            for (int mi = 0; mi < 4; mi++)
#pragma unroll
                for (int nj = 0; nj < 2; nj++) {
                    mma_bf16(acc[mi][2 * nj],     af[mi], &bf[nj][0]);
                    mma_bf16(acc[mi][2 * nj + 1], af[mi], &bf[nj][2]);
                }
        }
    }

    const int cl = 2 * (lane & 3);
    const int rl = lane >> 2;
#pragma unroll
    for (int mi = 0; mi < 4; mi++) {
        int row0 = m0 + m_w + mi * 16 + rl;
#pragma unroll
        for (int nt = 0; nt < 4; nt++) {
            int lc = n_w + nt * 8 + cl;
            int col = n0 + lc;
            float bx = bias_s[lc], by = bias_s[lc + 1];
            float2 v0 = {acc[mi][nt][0] + bx, acc[mi][nt][1] + by};
            float2 v1 = {acc[mi][nt][2] + bx, acc[mi][nt][3] + by};
            *(float2*)(g_trans + (size_t)row0 * NN + col) = v0;
            *(float2*)(g_trans + (size_t)(row0 + 8) * NN + col) = v1;
        }
    }
}

// ---------------------------------------------------------------------------
// Kernel 3: scan, DISTANCE-2 register prefetch with static 3-phase buffer
// rotation (zero register copies). Pipelined deferred normalization,
// 2 barriers/step. One CTA per batch, 512 threads.
// ---------------------------------------------------------------------------
__global__ __launch_bounds__(512, 1) void scan_kernel(const float* __restrict__ init_s,
                                                      float* __restrict__ out)
{
    __shared__ float s_nx[2][DD];
    __shared__ float red[16][DD];
    __shared__ float wsum[4];

    const int tid = threadIdx.x;
    const int wid = tid >> 5;
    const int lane = tid & 31;
    const int b = blockIdx.x;
    const int c = tid >> 5;              // 0..15 : 8-row chunk
    const int j = (tid & 31) * 4;        // 4-col group
    const float* Tb = g_trans + (size_t)b * TT * (DD * DD);

    if (tid < DD) s_nx[1][tid] = init_s[tid];

    float4 A[8], B[8], C[8];
#pragma unroll
    for (int ii = 0; ii < 8; ii++) {
        A[ii] = *(const float4*)(Tb + (size_t)0 * NN + (size_t)(c * 8 + ii) * DD + j);
        B[ii] = *(const float4*)(Tb + (size_t)1 * NN + (size_t)(c * 8 + ii) * DD + j);
    }
    __syncthreads();                     // BAR_A (t=0)

    // One scan step with static buffer roles: cur = data for step t,
    // n2 receives loads for t+2. (n1 is untouched; consumed next step.)
    auto do_step = [&](float4 (&cur)[8], float4 (&n2)[8], int t) {
        const int rb = (t & 1) ^ 1;      // state read buffer
        const int wb = t & 1;            // state write buffer

        if (t + 2 < TT) {
            const float* Tn = Tb + (size_t)(t + 2) * NN;
#pragma unroll
            for (int ii = 0; ii < 8; ii++)
                n2[ii] = *(const float4*)(Tn + (size_t)(c * 8 + ii) * DD + j);
        }

        float4 p = {0.0f, 0.0f, 0.0f, 0.0f};
#pragma unroll
        for (int ii = 0; ii < 8; ii++) {
            float sv = s_nx[rb][c * 8 + ii];
            p.x = fmaf(sv, cur[ii].x, p.x);
            p.y = fmaf(sv, cur[ii].y, p.y);
            p.z = fmaf(sv, cur[ii].z, p.z);
            p.w = fmaf(sv, cur[ii].w, p.w);
        }
        *(float4*)&red[c][j] = p;

        // warps 12-15: squared norm of current state
        if (wid >= 12) {
            const int k = wid - 12;
            float sv = s_nx[rb][k * 32 + lane];
            float sq = sv * sv;
#pragma unroll
            for (int o = 16; o; o >>= 1) sq += __shfl_xor_sync(0xffffffffu, sq, o);
            if (lane == 0) wsum[k] = sq;
        }
        __syncthreads();                 // BAR_B

        if (tid < DD) {
            float s0 = red[0][tid] + red[1][tid];
            float s1 = red[2][tid] + red[3][tid];
            float s2 = red[4][tid] + red[5][tid];
            float s3 = red[6][tid] + red[7][tid];
            float s4 = red[8][tid] + red[9][tid];
            float s5 = red[10][tid] + red[11][tid];
            float s6 = red[12][tid] + red[13][tid];
            float s7 = red[14][tid] + red[15][tid];
            float v = ((s0 + s1) + (s2 + s3)) + ((s4 + s5) + (s6 + s7));
            v = fmaxf(v, 0.0f);

            float inv = rsqrtf(fmaxf((wsum[0] + wsum[1]) + (wsum[2] + wsum[3]), 1e-24f));
            if (t > 0)
                out[((size_t)b * TT + (t - 1)) * DD + tid] = s_nx[rb][tid] * inv;
            s_nx[wb][tid] = v * inv;     // positive scale: exact (homogeneous)
        }
        __syncthreads();                 // BAR_A (next step)
    };

    // 510 = 3*170 steps with rotating roles, then 2 drain steps (rotation
    // period is 3, and 510 % 3 == 0 so the tail binding is (A,B,C),(B,C,A)).
#pragma unroll 1
    for (int t = 0; t < 510; t += 3) {
        do_step(A, C, t);
        do_step(B, A, t + 1);
        do_step(C, B, t + 2);
    }
    do_step(A, C, 510);
    do_step(B, A, 511);

    // drain: out[TT-1]
    const int fb = (TT - 1) & 1;
    if (wid >= 12) {
        const int k = wid - 12;
        float sv = s_nx[fb][k * 32 + lane];
        float sq = sv * sv;
#pragma unroll
        for (int o = 16; o; o >>= 1) sq += __shfl_xor_sync(0xffffffffu, sq, o);
        if (lane == 0) wsum[k] = sq;
    }
    __syncthreads();
    if (tid < DD) {
        float inv = rsqrtf(fmaxf((wsum[0] + wsum[1]) + (wsum[2] + wsum[3]), 1e-24f));
        out[((size_t)b * TT + (TT - 1)) * DD + tid] = s_nx[fb][tid] * inv;
    }
}

// ---------------------------------------------------------------------------
extern "C" void kernel_launch(void* const* d_in, const int* in_sizes, int n_in,
                              void* d_out, int out_size)
{
    const float* actions = (const float*)d_in[0];
    const float* init_s  = (const float*)d_in[1];
    const float* w1      = (const float*)d_in[2];
    const float* b1      = (const float*)d_in[3];
    const float* w2      = (const float*)d_in[4];
    const float* b2      = (const float*)d_in[5];
    float* out = (float*)d_out;

    cudaFuncSetAttribute(gemm7_kernel, cudaFuncAttributeMaxDynamicSharedMemorySize,
                         NSTG * STAGE_BYTES);

    mlp1_kernel<<<MM / 8, 256>>>(actions, w1, b1);
    bprep_kernel<<<dim3(NN / 32, KK / 32), dim3(32, 8)>>>(w2);
    gemm7_kernel<<<dim3(NN / BNG, MM / BMG), 256, NSTG * STAGE_BYTES>>>(b2);
    scan_kernel<<<BB, 512>>>(init_s, out);
}

// round 10
// speedup vs baseline: 1.0562x; 1.0562x over previous
#include <cuda_runtime.h>
#include <cuda_bf16.h>
#include <math.h>
#include <stdint.h>

// Shapes (fixed)
#define BB 32
#define TT 512
#define AA 64
#define DD 128
#define HH 256
#define MM (BB*TT)     // 16384
#define NN (DD*DD)     // 16384
#define KK HH          // 256
#define KP 512         // packed cols/row: per 32-k tile, [hi 32 | lo 32]

// Device scratch (allocation-free rule)
__device__ __align__(128) __nv_bfloat16 g_A2[(size_t)MM * KP];    // 16.7 MB
__device__ __align__(128) __nv_bfloat16 g_B2T[(size_t)NN * KP];   // 16.7 MB
__device__ __align__(128) float g_trans[(size_t)MM * NN];         // 1.07 GB

// ---------------------------------------------------------------------------
// PTX helpers (sm_80-class only — harness ptxas targets base sm_103)
// ---------------------------------------------------------------------------
__device__ __forceinline__ uint32_t smem_u32(const void* p) {
    uint32_t a;
    asm("{ .reg .u64 t; cvta.to.shared.u64 t, %1; cvt.u32.u64 %0, t; }" : "=r"(a) : "l"(p));
    return a;
}
__device__ __forceinline__ void cp16(uint32_t dst, const void* src) {
    asm volatile("cp.async.cg.shared.global [%0], [%1], 16;" :: "r"(dst), "l"(src) : "memory");
}
__device__ __forceinline__ void cp_commit() {
    asm volatile("cp.async.commit_group;" ::: "memory");
}
template <int N>
__device__ __forceinline__ void cp_wait() {
    asm volatile("cp.async.wait_group %0;" :: "n"(N) : "memory");
}
__device__ __forceinline__ void ldsm4(uint32_t* r, uint32_t addr) {
    asm volatile("ldmatrix.sync.aligned.m8n8.x4.shared.b16 {%0,%1,%2,%3}, [%4];"
                 : "=r"(r[0]), "=r"(r[1]), "=r"(r[2]), "=r"(r[3]) : "r"(addr));
}
__device__ __forceinline__ void mma_bf16(float* d, const uint32_t* a, const uint32_t* b) {
    asm volatile(
        "mma.sync.aligned.m16n8k16.row.col.f32.bf16.bf16.f32 "
        "{%0,%1,%2,%3}, {%4,%5,%6,%7}, {%8,%9}, {%0,%1,%2,%3};"
        : "+f"(d[0]), "+f"(d[1]), "+f"(d[2]), "+f"(d[3])
        : "r"(a[0]), "r"(a[1]), "r"(a[2]), "r"(a[3]), "r"(b[0]), "r"(b[1]));
}
// SW128 swizzle, closed form for row*128+kb (kb < 128)
__device__ __forceinline__ uint32_t swoff(uint32_t row, uint32_t kb) {
    return row * 128u + (kb ^ ((row & 7u) << 4));
}

// ---------------------------------------------------------------------------
// Kernel 1: h = relu(actions@w1+b1); write A2 packed [hi|lo] per 32-k tile
// ---------------------------------------------------------------------------
__global__ __launch_bounds__(256) void mlp1_kernel(const float* __restrict__ actions,
                                                   const float* __restrict__ w1,
                                                   const float* __restrict__ b1)
{
    __shared__ float as[8][AA];
    const int tid = threadIdx.x;
    const int m0 = blockIdx.x * 8;

    for (int i = tid; i < 8 * AA; i += 256)
        as[i >> 6][i & 63] = actions[(size_t)m0 * AA + i];
    __syncthreads();

    const int n = tid;                    // k index in [0,256)
    float bv = b1[n];
    float acc[8];
#pragma unroll
    for (int r = 0; r < 8; r++) acc[r] = bv;
#pragma unroll 8
    for (int a = 0; a < AA; a++) {
        float w = w1[(size_t)a * HH + n];
#pragma unroll
        for (int r = 0; r < 8; r++) acc[r] = fmaf(as[r][a], w, acc[r]);
    }
    const int koff = (n >> 5) * 64 + (n & 31);   // packed column of hi
#pragma unroll
    for (int r = 0; r < 8; r++) {
        float v = fmaxf(acc[r], 0.0f);
        __nv_bfloat16 hi = __float2bfloat16_rn(v);
        __nv_bfloat16 lo = __float2bfloat16_rn(v - __bfloat162float(hi));
        size_t row = (size_t)(m0 + r) * KP;
        g_A2[row + koff] = hi;
        g_A2[row + koff + 32] = lo;
    }
}

// ---------------------------------------------------------------------------
// Kernel 1b: B2T[n] packed [hi|lo] per 32-k tile (transpose of w2)
// ---------------------------------------------------------------------------
__global__ __launch_bounds__(256) void bprep_kernel(const float* __restrict__ w2)
{
    __shared__ float tile[32][33];
    const int tx = threadIdx.x;          // 0..31
    const int ty = threadIdx.y;          // 0..7
    const int n0 = blockIdx.x * 32;
    const int k0 = blockIdx.y * 32;
#pragma unroll
    for (int i = 0; i < 4; i++) {
        int k = k0 + ty + i * 8;
        tile[ty + i * 8][tx] = w2[(size_t)k * NN + n0 + tx];
    }
    __syncthreads();
    const int k = k0 + tx;
    const int koff = (k >> 5) * 64 + (k & 31);
#pragma unroll
    for (int i = 0; i < 4; i++) {
        int nrow = ty + i * 8;
        float v = tile[tx][nrow];        // w2[k, n0+nrow]
        __nv_bfloat16 hi = __float2bfloat16_rn(v);
        __nv_bfloat16 lo = __float2bfloat16_rn(v - __bfloat162float(hi));
        size_t row = (size_t)(n0 + nrow) * KP + koff;
        g_B2T[row] = hi;
        g_B2T[row + 32] = lo;
    }
}

// ---------------------------------------------------------------------------
// Kernel 2: bf16 mma.sync GEMM with shared-hi operand reuse.
// Per 32-real-k tile (128B rows = [hi 64B | lo 64B]), issue AHxBH, AHxBL,
// ALxBH from one fragment load set. BM=BN=128, NKT=8, 3-stage cp.async,
// 256 threads, 2 CTAs/SM. Operand L2 traffic: 4.3GB (was 6.4).
// ---------------------------------------------------------------------------
#define BMG 128
#define BNG 128
#define NKT 8            // 256 real k / 32 per tile
#define NSTG 3
#define A_BYTES (BMG*128)    // 16384
#define B_BYTES (BNG*128)    // 16384
#define STAGE_BYTES (A_BYTES + B_BYTES)  // 32768
#define ROWB (KP*2)          // 1024 bytes per packed row

__global__ __launch_bounds__(256, 2) void gemm8_kernel(const float* __restrict__ bias)
{
    extern __shared__ char dsm[];
    __shared__ float bias_s[BNG];

    const uint32_t dyn = smem_u32(dsm);
    const int tid = threadIdx.x;
    const int wid = tid >> 5;
    const int lane = tid & 31;
    const int m0 = blockIdx.y * BMG;
    const int n0 = blockIdx.x * BNG;

    if (tid < BNG) bias_s[tid] = bias[n0 + tid];

    const char* Abase = (const char*)g_A2;
    const char* Bbase = (const char*)g_B2T;

    auto load_stage = [&](int s, int kt) {
        uint32_t sb = dyn + s * STAGE_BYTES;
        size_t kbyte = (size_t)kt * 128;         // 128 B per packed k-tile
#pragma unroll
        for (int i = 0; i < 4; i++) {            // A: 1024 chunks of 16B
            int q = i * 256 + tid;
            uint32_t r = q >> 3, c = (q & 7) * 16;
            cp16(sb + swoff(r, c),
                 Abase + (size_t)(m0 + r) * ROWB + kbyte + c);
        }
#pragma unroll
        for (int i = 0; i < 4; i++) {            // B: 1024 chunks
            int q = i * 256 + tid;
            uint32_t r = q >> 3, c = (q & 7) * 16;
            cp16(sb + A_BYTES + swoff(r, c),
                 Bbase + (size_t)(n0 + r) * ROWB + kbyte + c);
        }
        cp_commit();
    };

    // prologue: 2 stages in flight
    load_stage(0, 0);
    load_stage(1, 1);

    // warp tiling: 2 (m) x 4 (n) warps, each 64x32
    const int m_w = (wid >> 2) * 64;
    const int n_w = (wid & 3) * 32;

    const uint32_t a_row = m_w + (lane & 7) + (lane & 8);          // + mi*16
    const uint32_t a_hk  = (lane >> 4) << 4;                       // 0/16
    const uint32_t b_row = n_w + (lane & 7) + ((lane >> 4) << 3);  // + nj*16
    const uint32_t b_hk  = (lane & 8) << 1;                        // 0/16

    float acc[4][4][4];
#pragma unroll
    for (int mi = 0; mi < 4; mi++)
#pragma unroll
        for (int nt = 0; nt < 4; nt++)
#pragma unroll
            for (int e = 0; e < 4; e++) acc[mi][nt][e] = 0.0f;

#pragma unroll 1
    for (int kt = 0; kt < NKT; kt++) {
        const int s = kt % NSTG;

        if (kt + 1 < NKT) cp_wait<1>();
        else              cp_wait<0>();
        __syncthreads();

        if (kt + 2 < NKT) load_stage((kt + 2) % NSTG, kt + 2);

        const uint32_t abase = dyn + s * STAGE_BYTES;
        const uint32_t bbase = abase + A_BYTES;

#pragma unroll
        for (int ks = 0; ks < 2; ks++) {         // two k16 chunks of the 32-k tile
            const uint32_t akb_h = ks * 32 + a_hk;       // hi bytes [0,64)
            const uint32_t bkb_h = ks * 32 + b_hk;
            uint32_t ah[4][4], bh[2][4];
            // hi fragments
#pragma unroll
            for (int mi = 0; mi < 4; mi++)
                ldsm4(ah[mi], abase + swoff(a_row + mi * 16, akb_h));
#pragma unroll
            for (int nj = 0; nj < 2; nj++)
                ldsm4(bh[nj], bbase + swoff(b_row + nj * 16, bkb_h));
            // pass 1: AH x BH
#pragma unroll
            for (int mi = 0; mi < 4; mi++)
#pragma unroll
                for (int nj = 0; nj < 2; nj++) {
                    mma_bf16(acc[mi][2 * nj],     ah[mi], &bh[nj][0]);
                    mma_bf16(acc[mi][2 * nj + 1], ah[mi], &bh[nj][2]);
                }
            // pass 2: AH x BL
            {
                uint32_t bl[2][4];
#pragma unroll
                for (int nj = 0; nj < 2; nj++)
                    ldsm4(bl[nj], bbase + swoff(b_row + nj * 16, 64 + bkb_h));
#pragma unroll
                for (int mi = 0; mi < 4; mi++)
#pragma unroll
                    for (int nj = 0; nj < 2; nj++) {
                        mma_bf16(acc[mi][2 * nj],     ah[mi], &bl[nj][0]);
                        mma_bf16(acc[mi][2 * nj + 1], ah[mi], &bl[nj][2]);
                    }
            }
            // pass 3: AL x BH (reuse ah storage for al)
#pragma unroll
            for (int mi = 0; mi < 4; mi++)
                ldsm4(ah[mi], abase + swoff(a_row + mi * 16, 64 + akb_h));
#pragma unroll
            for (int mi = 0; mi < 4; mi++)
#pragma unroll
                for (int nj = 0; nj < 2; nj++) {
                    mma_bf16(acc[mi][2 * nj],     ah[mi], &bh[nj][0]);
                    mma_bf16(acc[mi][2 * nj + 1], ah[mi], &bh[nj][2]);
                }
        }
    }

    // epilogue: direct float2 stores with bias
    const int cl = 2 * (lane & 3);
    const int rl = lane >> 2;
#pragma unroll
    for (int mi = 0; mi < 4; mi++) {
        int row0 = m0 + m_w + mi * 16 + rl;
#pragma unroll
        for (int nt = 0; nt < 4; nt++) {
            int lc = n_w + nt * 8 + cl;
            int col = n0 + lc;
            float bx = bias_s[lc], by = bias_s[lc + 1];
            float2 v0 = {acc[mi][nt][0] + bx, acc[mi][nt][1] + by};
            float2 v1 = {acc[mi][nt][2] + bx, acc[mi][nt][3] + by};
            *(float2*)(g_trans + (size_t)row0 * NN + col) = v0;
            *(float2*)(g_trans + (size_t)(row0 + 8) * NN + col) = v1;
        }
    }
}

// ---------------------------------------------------------------------------
// Kernel 3: scan (R8 measured-good version). Double-buffered state; warps
// 12-15 compute prior-state norm during matvec; 2 barriers/step; distance-1
// register prefetch.
// ---------------------------------------------------------------------------
__global__ __launch_bounds__(512, 1) void scan_kernel(const float* __restrict__ init_s,
                                                      float* __restrict__ out)
{
    __shared__ float s_nx[2][DD];
    __shared__ float red[16][DD];
    __shared__ float wsum[4];

    const int tid = threadIdx.x;
    const int wid = tid >> 5;
    const int lane = tid & 31;
    const int b = blockIdx.x;
    const int c = tid >> 5;              // 0..15 : 8-row chunk
    const int j = (tid & 31) * 4;        // 4-col group
    const float* Tb = g_trans + (size_t)b * TT * (DD * DD);

    if (tid < DD) s_nx[1][tid] = init_s[tid];

    float4 cur[8];
#pragma unroll
    for (int ii = 0; ii < 8; ii++)
        cur[ii] = *(const float4*)(Tb + (size_t)(c * 8 + ii) * DD + j);
    __syncthreads();                     // BAR_A (t=0)

    for (int t = 0; t < TT; t++) {
        const int rb = (t & 1) ^ 1;
        const int wb = t & 1;

        float4 nxt[8];
        if (t + 1 < TT) {
            const float* Tn = Tb + (size_t)(t + 1) * (DD * DD);
#pragma unroll
            for (int ii = 0; ii < 8; ii++)
                nxt[ii] = *(const float4*)(Tn + (size_t)(c * 8 + ii) * DD + j);
        }

        float4 p = {0.0f, 0.0f, 0.0f, 0.0f};
#pragma unroll
        for (int ii = 0; ii < 8; ii++) {
            float sv = s_nx[rb][c * 8 + ii];
            p.x = fmaf(sv, cur[ii].x, p.x);
            p.y = fmaf(sv, cur[ii].y, p.y);
            p.z = fmaf(sv, cur[ii].z, p.z);
            p.w = fmaf(sv, cur[ii].w, p.w);
        }
        *(float4*)&red[c][j] = p;

        if (wid >= 12) {
            const int k = wid - 12;
            float sv = s_nx[rb][k * 32 + lane];
            float sq = sv * sv;
#pragma unroll
            for (int o = 16; o; o >>= 1) sq += __shfl_xor_sync(0xffffffffu, sq, o);
            if (lane == 0) wsum[k] = sq;
        }
        __syncthreads();                 // BAR_B

        if (tid < DD) {
            float s0 = red[0][tid] + red[1][tid];
            float s1 = red[2][tid] + red[3][tid];
            float s2 = red[4][tid] + red[5][tid];
            float s3 = red[6][tid] + red[7][tid];
            float s4 = red[8][tid] + red[9][tid];
            float s5 = red[10][tid] + red[11][tid];
            float s6 = red[12][tid] + red[13][tid];
            float s7 = red[14][tid] + red[15][tid];
            float v = ((s0 + s1) + (s2 + s3)) + ((s4 + s5) + (s6 + s7));
            v = fmaxf(v, 0.0f);

            float inv = rsqrtf(fmaxf((wsum[0] + wsum[1]) + (wsum[2] + wsum[3]), 1e-24f));
            if (t > 0)
                out[((size_t)b * TT + (t - 1)) * DD + tid] = s_nx[rb][tid] * inv;
            s_nx[wb][tid] = v * inv;     // positive scale: exact (homogeneous)
        }
#pragma unroll
        for (int ii = 0; ii < 8; ii++) cur[ii] = nxt[ii];
        __syncthreads();                 // BAR_A (next step)
    }

    const int fb = (TT - 1) & 1;
    if (wid >= 12) {
        const int k = wid - 12;
        float sv = s_nx[fb][k * 32 + lane];
        float sq = sv * sv;
#pragma unroll
        for (int o = 16; o; o >>= 1) sq += __shfl_xor_sync(0xffffffffu, sq, o);
        if (lane == 0) wsum[k] = sq;
    }
    __syncthreads();
    if (tid < DD) {
        float inv = rsqrtf(fmaxf((wsum[0] + wsum[1]) + (wsum[2] + wsum[3]), 1e-24f));
        out[((size_t)b * TT + (TT - 1)) * DD + tid] = s_nx[fb][tid] * inv;
    }
}

// ---------------------------------------------------------------------------
extern "C" void kernel_launch(void* const* d_in, const int* in_sizes, int n_in,
                              void* d_out, int out_size)
{
    const float* actions = (const float*)d_in[0];
    const float* init_s  = (const float*)d_in[1];
    const float* w1      = (const float*)d_in[2];
    const float* b1      = (const float*)d_in[3];
    const float* w2      = (const float*)d_in[4];
    const float* b2      = (const float*)d_in[5];
    float* out = (float*)d_out;

    cudaFuncSetAttribute(gemm8_kernel, cudaFuncAttributeMaxDynamicSharedMemorySize,
                         NSTG * STAGE_BYTES);

    mlp1_kernel<<<MM / 8, 256>>>(actions, w1, b1);
    bprep_kernel<<<dim3(NN / 32, KK / 32), dim3(32, 8)>>>(w2);
    gemm8_kernel<<<dim3(NN / BNG, MM / BMG), 256, NSTG * STAGE_BYTES>>>(b2);
    scan_kernel<<<BB, 512>>>(init_s, out);
}